// round 15
// baseline (speedup 1.0000x reference)
#include <cuda_runtime.h>
#include <cuda_bf16.h>
#include <cuda_fp16.h>
#include <math.h>

#define NNZ   4096
#define HIDN  4096
#define NHEAD 32
#define NKVH  8
#define HDIM  128
#define SEQ   1024
#define NBATCH 4
#define QKVC  6144
#define KOFF  4096
#define VOFF  5120
#define VCOLS 1024

// ---------------- persistent scratch ----------------
__device__ float g_qkv[(size_t)NNZ * QKVC];
__device__ __nv_bfloat16 g_qkvh[(size_t)NNZ * QKVC];
__device__ __nv_bfloat16 g_qkvl[(size_t)NNZ * QKVC];
__device__ __half g_vf[(size_t)NNZ * VCOLS];          // V post-rope-pass, fp16
__device__ __half g_hidf[(size_t)NNZ * HIDN];         // hidden, fp16 single
__device__ __half g_wf[(size_t)QKVC * HIDN];          // fused [wq;wk;wv] fp16
__device__ __half g_woh[(size_t)HIDN * HIDN];         // wo, fp16 single
__device__ __half g_ath[(size_t)NNZ * HIDN];          // attention out, fp16

// ---------------- primitives ----------------
__device__ __forceinline__ void ldsm_x4(unsigned* r, unsigned addr) {
    asm volatile("ldmatrix.sync.aligned.m8n8.x4.shared.b16 {%0,%1,%2,%3}, [%4];\n"
                 : "=r"(r[0]), "=r"(r[1]), "=r"(r[2]), "=r"(r[3]) : "r"(addr));
}
__device__ __forceinline__ void ldsm_x4_t(unsigned* r, unsigned addr) {
    asm volatile("ldmatrix.sync.aligned.m8n8.x4.trans.shared.b16 {%0,%1,%2,%3}, [%4];\n"
                 : "=r"(r[0]), "=r"(r[1]), "=r"(r[2]), "=r"(r[3]) : "r"(addr));
}
__device__ __forceinline__ void mma_bf16(float* c, const unsigned* a, const unsigned* b) {
    asm volatile(
        "mma.sync.aligned.m16n8k16.row.col.f32.bf16.bf16.f32 "
        "{%0,%1,%2,%3}, {%4,%5,%6,%7}, {%8,%9}, {%0,%1,%2,%3};\n"
        : "+f"(c[0]), "+f"(c[1]), "+f"(c[2]), "+f"(c[3])
        : "r"(a[0]), "r"(a[1]), "r"(a[2]), "r"(a[3]), "r"(b[0]), "r"(b[1]));
}
__device__ __forceinline__ void mma_f16(float* c, const unsigned* a, const unsigned* b) {
    asm volatile(
        "mma.sync.aligned.m16n8k16.row.col.f32.f16.f16.f32 "
        "{%0,%1,%2,%3}, {%4,%5,%6,%7}, {%8,%9}, {%0,%1,%2,%3};\n"
        : "+f"(c[0]), "+f"(c[1]), "+f"(c[2]), "+f"(c[3])
        : "r"(a[0]), "r"(a[1]), "r"(a[2]), "r"(a[3]), "r"(b[0]), "r"(b[1]));
}
__device__ __forceinline__ unsigned pk(__nv_bfloat16 a, __nv_bfloat16 b) {
    __nv_bfloat162 t(a, b);
    return *reinterpret_cast<unsigned*>(&t);
}
__device__ __forceinline__ void cpa16(unsigned dst, const void* src) {
    asm volatile("cp.async.cg.shared.global [%0], [%1], 16;\n" :: "r"(dst), "l"(src));
}
__device__ __forceinline__ void cpa_commit() { asm volatile("cp.async.commit_group;\n"); }

// ---------------- conversion kernels ----------------
__global__ void half_kernel(const float* __restrict__ src,
                            __half* __restrict__ dst, int n)
{
    int i = (blockIdx.x * blockDim.x + threadIdx.x) * 4;
    if (i >= n) return;
    float4 v = *(const float4*)(src + i);
    __half2 a = __floats2half2_rn(v.x, v.y);
    __half2 b = __floats2half2_rn(v.z, v.w);
    *(uint2*)(dst + i) = make_uint2(*(unsigned*)&a, *(unsigned*)&b);
}

// RoPE + split for qkv. grid (NNZ, 48), block 64.
__global__ void split_rope_kernel(const float* __restrict__ qkv,
                                  const int* __restrict__ pos,
                                  __nv_bfloat16* __restrict__ qh,
                                  __nv_bfloat16* __restrict__ ql,
                                  __half* __restrict__ vf)
{
    const int tok = blockIdx.x;
    const int hb  = blockIdx.y;
    const int d   = threadIdx.x;
    const size_t base = (size_t)tok * QKVC + hb * HDIM;
    float x1 = qkv[base + d], x2 = qkv[base + d + 64];

    if (hb >= 40) {
        const size_t vb = (size_t)tok * VCOLS + (hb - 40) * HDIM;
        vf[vb + d]      = __float2half_rn(x1);
        vf[vb + d + 64] = __float2half_rn(x2);
        return;
    }

    float freq = exp2f(-0.29580575860567744f * (float)d);
    const float wl = 6.283185307179586f / freq;
    float f;
    if (wl < 2048.0f)       f = freq;
    else if (wl > 8192.0f)  f = freq * 0.125f;
    else {
        float smooth = (8192.0f / wl - 1.0f) * (1.0f / 3.0f);
        f = (1.0f - smooth) * freq * 0.125f + smooth * freq;
    }
    const float ang = (float)pos[tok] * f;
    const float c = cosf(ang), s = sinf(ang);
    float y1 = x1 * c - x2 * s;
    float y2 = x2 * c + x1 * s;
    if (hb < 32) { y1 *= 0.08838834764831845f; y2 *= 0.08838834764831845f; }

    __nv_bfloat16 h1 = __float2bfloat16(y1), h2 = __float2bfloat16(y2);
    qh[base + d]      = h1;
    qh[base + d + 64] = h2;
    ql[base + d]      = __float2bfloat16(y1 - __bfloat162float(h1));
    ql[base + d + 64] = __float2bfloat16(y2 - __bfloat162float(h2));
}

// ---------------------------------------------------------------------------
// Single-term fp16 GEMM: C = A B^T. CTA tile 128x256, 16 warps (4x4),
// warp tile 32x64 -> 16 mma per 6 ldsm per k16 (issue-ratio optimized).
// BK=32, 4-stage cp.async, one barrier per iteration.
// Grid: (N/256, M/128). N % 256 == 0, M % 128 == 0, K % 32 == 0.
// ---------------------------------------------------------------------------
#define GSTRIDE 40
#define A_BYTES (128 * GSTRIDE * 2)              // 10240
#define B_BYTES (256 * GSTRIDE * 2)              // 20480
#define NSTAGE 4
#define H_STAGE_BYTES (A_BYTES + B_BYTES)        // 30720
#define GEMMH_SMEM (NSTAGE * H_STAGE_BYTES)      // 122880

__global__ void __launch_bounds__(512) gemm_f16(
    const __half* __restrict__ A, const __half* __restrict__ B,
    float* __restrict__ C, int K, int ldc)
{
    extern __shared__ __half hsm[];
    const unsigned smb = (unsigned)__cvta_generic_to_shared(hsm);

    const int bm = blockIdx.y * 128;
    const int bn = blockIdx.x * 256;
    const int t  = threadIdx.x;
    const int lane = t & 31;
    const int warp = t >> 5;
    const int wm = (warp & 3) * 32;      // warp m-offset
    const int wn = (warp >> 2) * 64;     // warp n-offset

    // loader: A 128 rows x 4 chunks (512 chunks); B 256 rows x 4 chunks
    // (1024 chunks = 2/thread, rows ldRow and ldRow+128)
    const int ldRow = t >> 2;            // 0..127
    const int ldCh  = (t & 3) * 8;
    const size_t aOff  = (size_t)(bm + ldRow) * K + ldCh;
    const size_t bOff0 = (size_t)(bn + ldRow) * K + ldCh;
    const size_t bOff1 = (size_t)(bn + ldRow + 128) * K + ldCh;
    const unsigned dA  = (unsigned)(ldRow * GSTRIDE + ldCh) * 2u;
    const unsigned dB0 = A_BYTES + dA;
    const unsigned dB1 = A_BYTES + (unsigned)((ldRow + 128) * GSTRIDE + ldCh) * 2u;

    const int mat = lane >> 3;
    const int aRow = wm + (lane & 7) + (mat & 1) * 8;
    const int aColAdd = (mat >> 1) * 8;
    const int bRow = wn + (lane & 7) + (mat >> 1) * 8;
    const int bColAdd = (mat & 1) * 8;

    float acc[2][8][4];
#pragma unroll
    for (int mi = 0; mi < 2; mi++)
#pragma unroll
        for (int nj = 0; nj < 8; nj++)
#pragma unroll
            for (int u = 0; u < 4; u++) acc[mi][nj][u] = 0.0f;

    const int nt = K / 32;

#pragma unroll
    for (int s = 0; s < NSTAGE - 1; s++) {
        const unsigned st = smb + s * H_STAGE_BYTES;
        const int kn = s * 32;
        cpa16(st + dA,  A + aOff  + kn);
        cpa16(st + dB0, B + bOff0 + kn);
        cpa16(st + dB1, B + bOff1 + kn);
        cpa_commit();
    }

    for (int i = 0; i < nt; i++) {
        asm volatile("cp.async.wait_group %0;\n" :: "n"(NSTAGE - 2));
        __syncthreads();   // stage i visible; all warps done with stage i-1

        const unsigned st = smb + (i & (NSTAGE - 1)) * H_STAGE_BYTES;
        const unsigned bA = st;
        const unsigned bB = st + A_BYTES;

#pragma unroll
        for (int kk = 0; kk < 32; kk += 16) {
            unsigned a4[2][4], b4[16];
#pragma unroll
            for (int mi = 0; mi < 2; mi++) {
                unsigned off = (unsigned)((aRow + mi * 16) * GSTRIDE + kk + aColAdd) * 2u;
                ldsm_x4(a4[mi], bA + off);
            }
#pragma unroll
            for (int p = 0; p < 4; p++) {
                unsigned off = (unsigned)((bRow + p * 16) * GSTRIDE + kk + bColAdd) * 2u;
                ldsm_x4(&b4[p * 4], bB + off);
            }
#pragma unroll
            for (int mi = 0; mi < 2; mi++)
#pragma unroll
                for (int nj = 0; nj < 8; nj++)
                    mma_f16(acc[mi][nj], a4[mi], &b4[(nj >> 1) * 4 + (nj & 1) * 2]);
        }

        if (i + NSTAGE - 1 < nt) {
            const unsigned sw = smb + ((i + NSTAGE - 1) & (NSTAGE - 1)) * H_STAGE_BYTES;
            const int kn = (i + NSTAGE - 1) * 32;
            cpa16(sw + dA,  A + aOff  + kn);
            cpa16(sw + dB0, B + bOff0 + kn);
            cpa16(sw + dB1, B + bOff1 + kn);
        }
        cpa_commit();
    }

    const int g = lane >> 2;
    const int tq = lane & 3;
#pragma unroll
    for (int mi = 0; mi < 2; mi++) {
        const int row0 = bm + wm + mi * 16 + g;
#pragma unroll
        for (int nj = 0; nj < 8; nj++) {
            const int col = bn + wn + nj * 8 + tq * 2;
            *(float2*)(C + (size_t)row0 * ldc + col) =
                make_float2(acc[mi][nj][0], acc[mi][nj][1]);
            *(float2*)(C + (size_t)(row0 + 8) * ldc + col) =
                make_float2(acc[mi][nj][2], acc[mi][nj][3]);
        }
    }
}

// ---------------------------------------------------------------------------
// Flash attention: QK bf16x3, PV fp16 single x single. Unchanged (round 9).
// ---------------------------------------------------------------------------
#define ASD 136
#define QARR_B (128 * ASD * 2)
#define KARR_B (64 * ASD * 2)
#define KVSTAGE_B (3 * KARR_B)
#define ATT_SMEM (2 * QARR_B + 2 * KVSTAGE_B)   // 174080 B

__device__ __forceinline__ void kv_fill(
    unsigned stage_b, const __nv_bfloat16* qh, const __nv_bfloat16* ql,
    const __half* vf, int b, int kt, int kvh, int tid)
{
    for (int j = tid; j < 64 * 16; j += 256) {
        const int r = j >> 4, ch = (j & 15) * 8;
        const int ktok = b * SEQ + kt * 64 + r;
        const size_t ki = (size_t)ktok * QKVC + KOFF + kvh * HDIM + ch;
        const size_t vi = (size_t)ktok * VCOLS + kvh * HDIM + ch;
        const unsigned dst = stage_b + (unsigned)(r * ASD + ch) * 2u;
        cpa16(dst,              qh + ki);
        cpa16(dst + KARR_B,     ql + ki);
        cpa16(dst + 2 * KARR_B, vf + vi);
    }
}

__global__ void __launch_bounds__(256) attn_tc(
    const __nv_bfloat16* __restrict__ qh, const __nv_bfloat16* __restrict__ ql,
    const __half* __restrict__ vf, __half* __restrict__ oh)
{
    extern __shared__ __nv_bfloat16 smA[];
    const unsigned smb = (unsigned)__cvta_generic_to_shared(smA);

    const int qt  = (int)gridDim.x - 1 - (int)blockIdx.x;
    const int h   = blockIdx.y;
    const int b   = blockIdx.z;
    const int kvh = h >> 2;
    const int tid = threadIdx.x;
    const int lane = tid & 31;
    const int warp = tid >> 5;
    const int qr0 = qt * 128;
    const int mat = lane >> 3;
    const int lm7 = lane & 7;
    const int g   = lane >> 2;
    const int tq  = lane & 3;

    const int nkt = 2 * qt + 2;

    kv_fill(smb + 2 * QARR_B, qh, ql, vf, b, 0, kvh, tid);
    cpa_commit();
    kv_fill(smb + 2 * QARR_B + KVSTAGE_B, qh, ql, vf, b, 1, kvh, tid);
    cpa_commit();

    for (int j = tid; j < 128 * 16; j += 256) {
        const int r = j >> 4, ch = (j & 15) * 8;
        const size_t gi = (size_t)(b * SEQ + qr0 + r) * QKVC + h * HDIM + ch;
        *(uint4*)&smA[r * ASD + ch]              = *(const uint4*)&qh[gi];
        *(uint4*)&smA[128 * ASD + r * ASD + ch]  = *(const uint4*)&ql[gi];
    }

    float o[16][4];
#pragma unroll
    for (int nt = 0; nt < 16; nt++)
#pragma unroll
        for (int u = 0; u < 4; u++) o[nt][u] = 0.0f;
    float m0 = -1e30f, m1 = -1e30f, l0 = 0.0f, l1 = 0.0f;

    for (int kt = 0; kt < nkt; kt++) {
        const int s = kt & 1;
        if (kt + 1 < nkt) asm volatile("cp.async.wait_group 1;\n" ::: "memory");
        else              asm volatile("cp.async.wait_group 0;\n" ::: "memory");
        __syncthreads();

        const unsigned OKH = (unsigned)(2 * QARR_B + s * KVSTAGE_B);
        const unsigned OKL = OKH + KARR_B;
        const unsigned OVF = OKH + 2 * KARR_B;

        float sc[8][4];
#pragma unroll
        for (int nj = 0; nj < 8; nj++)
#pragma unroll
            for (int u = 0; u < 4; u++) sc[nj][u] = 0.0f;

#pragma unroll
        for (int kk = 0; kk < 128; kk += 16) {
            unsigned ah4[4], al4[4], bh[16], bl[16];
            const unsigned aoff =
                (unsigned)((warp * 16 + lm7 + (mat & 1) * 8) * ASD + kk + (mat >> 1) * 8) * 2u;
            ldsm_x4(ah4, smb + aoff);
            ldsm_x4(al4, smb + QARR_B + aoff);
#pragma unroll
            for (int p = 0; p < 4; p++) {
                const unsigned boff =
                    (unsigned)((p * 16 + lm7 + (mat >> 1) * 8) * ASD + kk + (mat & 1) * 8) * 2u;
                ldsm_x4(&bh[p * 4], OKH + smb + boff);
                ldsm_x4(&bl[p * 4], OKL + smb + boff);
            }
#pragma unroll
            for (int nj = 0; nj < 8; nj++) {
                const unsigned* b1 = &bh[(nj >> 1) * 4 + (nj & 1) * 2];
                const unsigned* b2 = &bl[(nj >> 1) * 4 + (nj & 1) * 2];
                mma_bf16(sc[nj], ah4, b1);
                mma_bf16(sc[nj], ah4, b2);
                mma_bf16(sc[nj], al4, b1);
            }
        }

        if (kt >= 2 * qt) {
            const int koff = kt * 64 - qr0;
            const int r0 = warp * 16 + g, r1 = r0 + 8;
#pragma unroll
            for (int nj = 0; nj < 8; nj++)
#pragma unroll
                for (int e = 0; e < 2; e++) {
                    const int cidx = nj * 8 + tq * 2 + e + koff;
                    if (cidx > r0) sc[nj][e]     = -1e30f;
                    if (cidx > r1) sc[nj][2 + e] = -1e30f;
                }
        }

        float mx0 = -1e30f, mx1 = -1e30f;
#pragma unroll
        for (int nj = 0; nj < 8; nj++) {
            mx0 = fmaxf(mx0, fmaxf(sc[nj][0], sc[nj][1]));
            mx1 = fmaxf(mx1, fmaxf(sc[nj][2], sc[nj][3]));
        }
        mx0 = fmaxf(mx0, __shfl_xor_sync(0xffffffffu, mx0, 1));
        mx0 = fmaxf(mx0, __shfl_xor_sync(0xffffffffu, mx0, 2));
        mx1 = fmaxf(mx1, __shfl_xor_sync(0xffffffffu, mx1, 1));
        mx1 = fmaxf(mx1, __shfl_xor_sync(0xffffffffu, mx1, 2));

        const float mn0 = fmaxf(m0, mx0), mn1 = fmaxf(m1, mx1);
        const float f0 = __expf(m0 - mn0), f1 = __expf(m1 - mn1);
        m0 = mn0; m1 = mn1;

        float s0 = 0.0f, s1 = 0.0f;
        unsigned pa[4][4];
#pragma unroll
        for (int nj = 0; nj < 8; nj++) {
            const float p0 = __expf(sc[nj][0] - m0);
            const float p1 = __expf(sc[nj][1] - m0);
            const float p2 = __expf(sc[nj][2] - m1);
            const float p3 = __expf(sc[nj][3] - m1);
            s0 += p0 + p1;  s1 += p2 + p3;
            __half2 a01 = __floats2half2_rn(p0, p1);
            __half2 a23 = __floats2half2_rn(p2, p3);
            const int kb = nj >> 1, hf = (nj & 1) * 2;
            pa[kb][hf + 0] = *(unsigned*)&a01;
            pa[kb][hf + 1] = *(unsigned*)&a23;
        }
        s0 += __shfl_xor_sync(0xffffffffu, s0, 1);
        s0 += __shfl_xor_sync(0xffffffffu, s0, 2);
        s1 += __shfl_xor_sync(0xffffffffu, s1, 1);
        s1 += __shfl_xor_sync(0xffffffffu, s1, 2);
        l0 = l0 * f0 + s0;
        l1 = l1 * f1 + s1;
#pragma unroll
        for (int nt = 0; nt < 16; nt++) {
            o[nt][0] *= f0; o[nt][1] *= f0;
            o[nt][2] *= f1; o[nt][3] *= f1;
        }

#pragma unroll
        for (int kb = 0; kb < 4; kb++) {
#pragma unroll
            for (int ng = 0; ng < 8; ng++) {
                const unsigned voff =
                    (unsigned)((kb * 16 + (mat & 1) * 8 + lm7) * ASD + ng * 16 + (mat >> 1) * 8) * 2u;
                unsigned v4[4];
                ldsm_x4_t(v4, OVF + smb + voff);
                mma_f16(o[2 * ng],     pa[kb], v4);
                mma_f16(o[2 * ng + 1], pa[kb], v4 + 2);
            }
        }

        __syncthreads();
        if (kt + 2 < nkt) {
            kv_fill(smb + 2 * QARR_B + s * KVSTAGE_B, qh, ql, vf, b, kt + 2, kvh, tid);
        }
        cpa_commit();
    }

    const float i0 = 1.0f / l0, i1 = 1.0f / l1;
    const size_t row0 = (size_t)(b * SEQ + qr0 + warp * 16 + g);
    const size_t row1 = row0 + 8;
#pragma unroll
    for (int nt = 0; nt < 16; nt++) {
        const int col = h * HDIM + nt * 8 + tq * 2;
        __half2 v01 = __floats2half2_rn(o[nt][0] * i0, o[nt][1] * i0);
        __half2 v23 = __floats2half2_rn(o[nt][2] * i1, o[nt][3] * i1);
        *(unsigned*)&oh[row0 * HIDN + col] = *(unsigned*)&v01;
        *(unsigned*)&oh[row1 * HIDN + col] = *(unsigned*)&v23;
    }
}

// ---------------------------------------------------------------------------
extern "C" void kernel_launch(void* const* d_in, const int* in_sizes, int n_in,
                              void* d_out, int out_size)
{
    const float* hidden = (const float*)d_in[0];
    const float* wq     = (const float*)d_in[1];
    const float* wk     = (const float*)d_in[2];
    const float* wv     = (const float*)d_in[3];
    const float* wo     = (const float*)d_in[4];
    const int*   pos    = (const int*)d_in[6];
    float*       outp   = (float*)d_out;

    float* qkv;  cudaGetSymbolAddress((void**)&qkv,  g_qkv);
    __nv_bfloat16 *qkvh, *qkvl;
    __half *hidf, *wf, *woh, *ath, *vfp;
    cudaGetSymbolAddress((void**)&qkvh, g_qkvh);
    cudaGetSymbolAddress((void**)&qkvl, g_qkvl);
    cudaGetSymbolAddress((void**)&hidf, g_hidf);
    cudaGetSymbolAddress((void**)&wf,  g_wf);
    cudaGetSymbolAddress((void**)&woh, g_woh);
    cudaGetSymbolAddress((void**)&ath, g_ath);
    cudaGetSymbolAddress((void**)&vfp, g_vf);

    cudaFuncSetAttribute(gemm_f16, cudaFuncAttributeMaxDynamicSharedMemorySize, GEMMH_SMEM);
    cudaFuncSetAttribute(attn_tc,  cudaFuncAttributeMaxDynamicSharedMemorySize, ATT_SMEM);

    const int nHid = NNZ * HIDN;
    const int nWqo = HIDN * HIDN;
    const int nWkv = 1024 * HIDN;
    half_kernel<<<nHid / 1024, 256>>>(hidden, hidf, nHid);
    half_kernel<<<nWqo / 1024, 256>>>(wq, wf,                       nWqo);
    half_kernel<<<nWkv / 1024, 256>>>(wk, wf + (size_t)KOFF * HIDN, nWkv);
    half_kernel<<<nWkv / 1024, 256>>>(wv, wf + (size_t)VOFF * HIDN, nWkv);
    half_kernel<<<nWqo / 1024, 256>>>(wo, woh, nWqo);

    // Fused QKV projection (fp16 single-term): [4096 x 6144], 128x256 tiles
    gemm_f16<<<dim3(QKVC / 256, NNZ / 128), 512, GEMMH_SMEM>>>(hidf, wf, qkv, HIDN, QKVC);

    // RoPE (+Q prescale) -> bf16 hi/lo; V -> fp16
    split_rope_kernel<<<dim3(NNZ, 48), 64>>>(qkv, pos, qkvh, qkvl, vfp);

    // Flash attention -> fp16 output
    attn_tc<<<dim3(SEQ / 128, NHEAD, NBATCH), 256, ATT_SMEM>>>(qkvh, qkvl, vfp, ath);

    // Output projection: fp16 single-term, 128x256 tiles
    gemm_f16<<<dim3(HIDN / 256, NNZ / 128), 512, GEMMH_SMEM>>>(ath, woh, outp, HIDN, HIDN);
}